// round 12
// baseline (speedup 1.0000x reference)
#include <cuda_runtime.h>
#include <cuda_bf16.h>
#include <cstdint>

namespace {
constexpr int Bn = 32;
constexpr int Tn = 1024;
constexpr int M  = Bn * 1024;

constexpr int Lc = 16;
constexpr int Cc = Tn / Lc;         // 64

constexpr int SZ  = 512 * 512;
constexpr int SZW = 256 * 512;      // words per packed matrix (either style)
constexpr int WST = 20;             // smem row stride in words
constexpr int BUFW = 7680;          // Ah 2560 | Al 2560 | Bh 1280 | Bl 1280
constexpr int SMEM_BYTES = 2 * BUFW * 4;   // 61440
}

// ---------------------------------------------------------------------------
// Static device scratch
//  B-style packed: word (w,n) at w*512+n  (pairs of k-ROWS)
//  A-style packed: word (row,w) at row*256+w (pairs of k-COLUMNS within a row)
// ---------------------------------------------------------------------------
__device__ uint32_t g_Rh[16 * SZW],  g_Rl[16 * SZW];    // R^1..R^16 B-style
__device__ uint32_t g_RAh[16 * SZW], g_RAl[16 * SZW];   // R^1..R^16 A-style
__device__ uint32_t g_Sh[5 * SZW],   g_Sl[5 * SZW];     // S^2..S^32 B-style
__device__ uint32_t g_SAh[5 * SZW],  g_SAl[5 * SZW];    // A-style
__device__ uint32_t g_Wh[SZW],       g_Wl[SZW];
__device__ uint32_t g_OA0h[2048 * 256], g_OA0l[2048 * 256];  // O-slice ping
__device__ uint32_t g_OA1h[2048 * 256], g_OA1l[2048 * 256];  // O-slice pong
__device__ float    g_V0[2048 * 512], g_V1[2048 * 512];
__device__ uint32_t g_V0Ah[2048 * 256], g_V0Al[2048 * 256];
__device__ uint32_t g_V1Ah[2048 * 256], g_V1Al[2048 * 256];

// ---------------------------------------------------------------------------
// helpers
// ---------------------------------------------------------------------------
__device__ __forceinline__ uint32_t packbf(float a, float b) {
    uint32_t r;  // low half = a, high half = b
    asm("cvt.rn.bf16x2.f32 %0, %1, %2;" : "=r"(r) : "f"(b), "f"(a));
    return r;
}
__device__ __forceinline__ float lo_f(uint32_t p) { return __uint_as_float(p << 16); }
__device__ __forceinline__ float hi_f(uint32_t p) { return __uint_as_float(p & 0xFFFF0000u); }

__device__ __forceinline__ void mma16816(float* c, const uint32_t* a,
                                         uint32_t b0, uint32_t b1) {
    asm volatile(
        "mma.sync.aligned.m16n8k16.row.col.f32.bf16.bf16.f32 "
        "{%0,%1,%2,%3}, {%4,%5,%6,%7}, {%8,%9}, {%0,%1,%2,%3};"
        : "+f"(c[0]), "+f"(c[1]), "+f"(c[2]), "+f"(c[3])
        : "r"(a[0]), "r"(a[1]), "r"(a[2]), "r"(a[3]), "r"(b0), "r"(b1));
}

__device__ __forceinline__ void ldsm4(uint32_t& r0, uint32_t& r1,
                                      uint32_t& r2, uint32_t& r3, uint32_t addr) {
    asm volatile(
        "ldmatrix.sync.aligned.m8n8.x4.shared.b16 {%0,%1,%2,%3}, [%4];"
        : "=r"(r0), "=r"(r1), "=r"(r2), "=r"(r3) : "r"(addr));
}

// shared compute: one 32-k chunk from staged smem buffer
__device__ __forceinline__ void compute_chunk(uint32_t base, int mo, int no,
                                              int aoffw, int boffw, float acc[2][4][4])
{
#pragma unroll
    for (int s = 0; s < 2; s++) {
        const int ws = s * 8;
        uint32_t aH[2][4], aL[2][4];
#pragma unroll
        for (int mf = 0; mf < 2; mf++) {
            const uint32_t wa = base + (uint32_t)(((mo + mf * 16) * WST + ws + aoffw) * 4);
            ldsm4(aH[mf][0], aH[mf][1], aH[mf][2], aH[mf][3], wa);
            ldsm4(aL[mf][0], aL[mf][1], aL[mf][2], aL[mf][3], wa + 2560u * 4u);
        }
#pragma unroll
        for (int p = 0; p < 2; p++) {
            const uint32_t wb = base +
                (uint32_t)((5120 + (no + p * 16) * WST + ws + boffw) * 4);
            uint32_t h0, h1, h2, h3, l0, l1, l2, l3;
            ldsm4(h0, h1, h2, h3, wb);
            ldsm4(l0, l1, l2, l3, wb + 1280u * 4u);
#pragma unroll
            for (int mf = 0; mf < 2; mf++) {
                mma16816(acc[mf][2 * p],     aH[mf], h0, h1);
                mma16816(acc[mf][2 * p],     aH[mf], l0, l1);
                mma16816(acc[mf][2 * p],     aL[mf], h0, h1);
                mma16816(acc[mf][2 * p + 1], aH[mf], h2, h3);
                mma16816(acc[mf][2 * p + 1], aH[mf], l2, l3);
                mma16816(acc[mf][2 * p + 1], aL[mf], h2, h3);
            }
        }
    }
}

// ---------------------------------------------------------------------------
// Core variant 1: fp32 A (converted in-kernel).  Used by XW only.
// arow: thread A ptr (row = tid>>1, k-offset (tid&1)*16)
// ---------------------------------------------------------------------------
__device__ __forceinline__ void hmma_core_bb(const float* __restrict__ arow,
                                             const uint32_t* __restrict__ bh,
                                             const uint32_t* __restrict__ bl,
                                             float acc[2][4][4])
{
    extern __shared__ uint32_t sw[];
    const uint32_t sb = (uint32_t)__cvta_generic_to_shared(sw);
    const int tid  = threadIdx.x;
    const int lane = tid & 31, wid = tid >> 5;
    const int mo = (wid >> 1) * 32, no = (wid & 1) * 32;
    const int sar = tid >> 1, saw = (tid & 1) * 8, sbw = (tid >> 6) * 4;
    const int aoffw = (lane & 15) * WST + (lane >> 4) * 4;
    const int jj = lane >> 3, iL = lane & 7;
    const int boffw = ((jj >> 1) * 8 + iL) * WST + (jj & 1) * 4;

    float af[16];
    uint32_t bhw[4], blw[4];

    auto LOAD = [&](int kc) {
        const float* ap = arow + kc * 32;
        float4 v;
        v = *(const float4*)(ap + 0);  af[0] = v.x;  af[1] = v.y;  af[2] = v.z;  af[3] = v.w;
        v = *(const float4*)(ap + 4);  af[4] = v.x;  af[5] = v.y;  af[6] = v.z;  af[7] = v.w;
        v = *(const float4*)(ap + 8);  af[8] = v.x;  af[9] = v.y;  af[10] = v.z; af[11] = v.w;
        v = *(const float4*)(ap + 12); af[12] = v.x; af[13] = v.y; af[14] = v.z; af[15] = v.w;
        const int off = (kc * 16 + sbw) * 512;
        bhw[0] = bh[off];        bhw[1] = bh[off + 512];
        bhw[2] = bh[off + 1024]; bhw[3] = bh[off + 1536];
        blw[0] = bl[off];        blw[1] = bl[off + 512];
        blw[2] = bl[off + 1024]; blw[3] = bl[off + 1536];
    };
    auto STORE = [&](int bi) {
        uint32_t h[8], l[8];
#pragma unroll
        for (int j = 0; j < 8; j++) {
            h[j] = packbf(af[2 * j], af[2 * j + 1]);
            l[j] = packbf(af[2 * j] - lo_f(h[j]), af[2 * j + 1] - hi_f(h[j]));
        }
        uint32_t* pA = sw + bi * BUFW + sar * WST + saw;
        *(uint4*)pA        = make_uint4(h[0], h[1], h[2], h[3]);
        *(uint4*)(pA + 4)  = make_uint4(h[4], h[5], h[6], h[7]);
        uint32_t* pAl = pA + 2560;
        *(uint4*)pAl       = make_uint4(l[0], l[1], l[2], l[3]);
        *(uint4*)(pAl + 4) = make_uint4(l[4], l[5], l[6], l[7]);
        uint32_t* pB = sw + bi * BUFW + 5120 + (tid & 63) * WST + sbw;
        *(uint4*)pB          = make_uint4(bhw[0], bhw[1], bhw[2], bhw[3]);
        *(uint4*)(pB + 1280) = make_uint4(blw[0], blw[1], blw[2], blw[3]);
    };

    LOAD(0); STORE(0); __syncthreads();
    int cur = 0;
    for (int kc = 0; kc < 16; kc++) {
        if (kc < 15) LOAD(kc + 1);
        compute_chunk(sb + (uint32_t)(cur * BUFW) * 4u, mo, no, aoffw, boffw, acc);
        if (kc < 15) { STORE(cur ^ 1); __syncthreads(); cur ^= 1; }
    }
}

// ---------------------------------------------------------------------------
// Core variant 2: pre-packed A (A-style hi/lo word arrays).
// aph/apl: per-thread row base = base + row*256 + (tid&1)*8
// ---------------------------------------------------------------------------
__device__ __forceinline__ void hmma_core_pp(const uint32_t* __restrict__ aph,
                                             const uint32_t* __restrict__ apl,
                                             const uint32_t* __restrict__ bh,
                                             const uint32_t* __restrict__ bl,
                                             float acc[2][4][4])
{
    extern __shared__ uint32_t sw[];
    const uint32_t sb = (uint32_t)__cvta_generic_to_shared(sw);
    const int tid  = threadIdx.x;
    const int lane = tid & 31, wid = tid >> 5;
    const int mo = (wid >> 1) * 32, no = (wid & 1) * 32;
    const int sar = tid >> 1, saw = (tid & 1) * 8, sbw = (tid >> 6) * 4;
    const int aoffw = (lane & 15) * WST + (lane >> 4) * 4;
    const int jj = lane >> 3, iL = lane & 7;
    const int boffw = ((jj >> 1) * 8 + iL) * WST + (jj & 1) * 4;

    uint4 ah0, ah1, al0, al1;
    uint32_t bhw[4], blw[4];

    auto LOAD = [&](int kc) {
        ah0 = *(const uint4*)(aph + kc * 16);
        ah1 = *(const uint4*)(aph + kc * 16 + 4);
        al0 = *(const uint4*)(apl + kc * 16);
        al1 = *(const uint4*)(apl + kc * 16 + 4);
        const int off = (kc * 16 + sbw) * 512;
        bhw[0] = bh[off];        bhw[1] = bh[off + 512];
        bhw[2] = bh[off + 1024]; bhw[3] = bh[off + 1536];
        blw[0] = bl[off];        blw[1] = bl[off + 512];
        blw[2] = bl[off + 1024]; blw[3] = bl[off + 1536];
    };
    auto STORE = [&](int bi) {
        uint32_t* pA = sw + bi * BUFW + sar * WST + saw;
        *(uint4*)pA        = ah0;
        *(uint4*)(pA + 4)  = ah1;
        uint32_t* pAl = pA + 2560;
        *(uint4*)pAl       = al0;
        *(uint4*)(pAl + 4) = al1;
        uint32_t* pB = sw + bi * BUFW + 5120 + (tid & 63) * WST + sbw;
        *(uint4*)pB          = make_uint4(bhw[0], bhw[1], bhw[2], bhw[3]);
        *(uint4*)(pB + 1280) = make_uint4(blw[0], blw[1], blw[2], blw[3]);
    };

    LOAD(0); STORE(0); __syncthreads();
    int cur = 0;
    for (int kc = 0; kc < 16; kc++) {
        if (kc < 15) LOAD(kc + 1);
        compute_chunk(sb + (uint32_t)(cur * BUFW) * 4u, mo, no, aoffw, boffw, acc);
        if (kc < 15) { STORE(cur ^ 1); __syncthreads(); cur ^= 1; }
    }
}

// A-style packed write of a float2 at (row, even col)
__device__ __forceinline__ void write_pka(uint32_t* __restrict__ dh,
                                          uint32_t* __restrict__ dl,
                                          int row, int col, float ex, float ey)
{
    const size_t pw = (size_t)row * 256 + (col >> 1);
    const uint32_t hh = packbf(ex, ey);
    dh[pw] = hh;
    dl[pw] = packbf(ex - lo_f(hh), ey - hi_f(hh));
}

// ---------------------------------------------------------------------------
// XW: C = X @ W, plus predicated A-style packed write of chunk-slice 0.
// grid (8, 256)
// ---------------------------------------------------------------------------
__global__ __launch_bounds__(256, 2) void hmma_gemm_xw(
    const float* __restrict__ A, const uint32_t* __restrict__ Bh,
    const uint32_t* __restrict__ Bl, float* __restrict__ C,
    uint32_t* __restrict__ OA0h, uint32_t* __restrict__ OA0l)
{
    const int bn = blockIdx.x * 64;
    const int bm = blockIdx.y * 128;
    const int tid = threadIdx.x;
    const float* arow = A + (size_t)(bm + (tid >> 1)) * 512 + (tid & 1) * 16;
    float acc[2][4][4] = {};
    hmma_core_bb(arow, Bh + bn + (tid & 63), Bl + bn + (tid & 63), acc);

    const int lane = tid & 31, wid = tid >> 5;
    const int g = lane >> 2, qi = lane & 3;
    const int mo = (wid >> 1) * 32, no = (wid & 1) * 32;
#pragma unroll
    for (int mf = 0; mf < 2; mf++)
#pragma unroll
        for (int f = 0; f < 4; f++) {
            const int r0  = bm + mo + mf * 16 + g;
            const int col = bn + no + f * 8 + 2 * qi;
            *(float2*)(C + (size_t)r0 * 512 + col) =
                make_float2(acc[mf][f][0], acc[mf][f][1]);
            *(float2*)(C + (size_t)(r0 + 8) * 512 + col) =
                make_float2(acc[mf][f][2], acc[mf][f][3]);
#pragma unroll
            for (int h = 0; h < 2; h++) {
                const int r = r0 + h * 8;
                const int time = r & 1023;
                if ((time & 15) == 0) {
                    const int pr = (time >> 4) * 32 + (r >> 10);
                    write_pka(OA0h, OA0l, pr, col, acc[mf][f][2 * h], acc[mf][f][2 * h + 1]);
                }
            }
        }
}

// ---------------------------------------------------------------------------
// Mega step: y<16 -> pass1 (packed-A in, fp32 O + packed-A out);
//            y>=16 -> ladder (packed-A in, dual packed out).
// ---------------------------------------------------------------------------
__global__ __launch_bounds__(256, 2) void mega_step_kernel(
    const uint32_t* __restrict__ Rbh, const uint32_t* __restrict__ Rbl,
    float* __restrict__ O, int t, float* __restrict__ V0,
    const uint32_t* __restrict__ OAinh, const uint32_t* __restrict__ OAinl,
    uint32_t* __restrict__ OAouth, uint32_t* __restrict__ OAoutl,
    const uint32_t* __restrict__ LAh, const uint32_t* __restrict__ LAl,
    const uint32_t* __restrict__ LBh, const uint32_t* __restrict__ LBl,
    uint32_t* __restrict__ LCbh, uint32_t* __restrict__ LCbl,
    uint32_t* __restrict__ LCah, uint32_t* __restrict__ LCal)
{
    const int bn  = blockIdx.x * 64;
    const int tid = threadIdx.x;
    const int lane = tid & 31, wid = tid >> 5;
    const int g = lane >> 2, qi = lane & 3;
    const int mo = (wid >> 1) * 32, no = (wid & 1) * 32;

    if (blockIdx.y < 16) {
        const int bm = blockIdx.y * 128;
        const int row = bm + (tid >> 1);
        const uint32_t* aph = OAinh + (size_t)row * 256 + (tid & 1) * 8;
        const uint32_t* apl = OAinl + (size_t)row * 256 + (tid & 1) * 8;
        float acc[2][4][4] = {};
        hmma_core_pp(aph, apl, Rbh + bn + (tid & 63), Rbl + bn + (tid & 63), acc);

#pragma unroll
        for (int mf = 0; mf < 2; mf++)
#pragma unroll
            for (int f = 0; f < 4; f++) {
                const int col = bn + no + f * 8 + 2 * qi;
#pragma unroll
                for (int h = 0; h < 2; h++) {
                    const int r = bm + mo + mf * 16 + g + h * 8;
                    float* op = O + ((size_t)(r & 31) * Tn + (size_t)(r >> 5) * Lc + t) * 512 + col;
                    float2 e = *(float2*)op;
                    e.x += acc[mf][f][2 * h];
                    e.y += acc[mf][f][2 * h + 1];
                    *(float2*)op = e;
                    write_pka(OAouth, OAoutl, r, col, e.x, e.y);
                    if (t == Lc - 1)
                        *(float2*)(V0 + (size_t)r * 512 + col) = e;
                }
            }
    } else {
        const int y2 = blockIdx.y - 16;
        const int z  = y2 >> 2;
        const int mrow = (y2 & 3) * 128;
        const int row = mrow + (tid >> 1);
        const uint32_t* aph = LAh + (size_t)z * SZW + (size_t)row * 256 + (tid & 1) * 8;
        const uint32_t* apl = LAl + (size_t)z * SZW + (size_t)row * 256 + (tid & 1) * 8;
        float acc[2][4][4] = {};
        hmma_core_pp(aph, apl, LBh + bn + (tid & 63), LBl + bn + (tid & 63), acc);

        uint32_t* Dbh = LCbh + (size_t)z * SZW;
        uint32_t* Dbl = LCbl + (size_t)z * SZW;
        uint32_t* Dah = LCah + (size_t)z * SZW;
        uint32_t* Dal = LCal + (size_t)z * SZW;
#pragma unroll
        for (int mf = 0; mf < 2; mf++)
#pragma unroll
            for (int f = 0; f < 4; f++) {
                const int r0  = mrow + mo + mf * 16 + g;
                const int col = bn + no + f * 8 + 2 * qi;
                // A-style direct
#pragma unroll
                for (int h = 0; h < 2; h++)
                    write_pka(Dah, Dal, r0 + h * 8, col,
                              acc[mf][f][2 * h], acc[mf][f][2 * h + 1]);
                // B-style via row-pair shuffle
                float pc0 = __shfl_sync(0xffffffffu, acc[mf][f][0], (lane + 4) & 31);
                float pc1 = __shfl_sync(0xffffffffu, acc[mf][f][1], (lane + 4) & 31);
                float pc2 = __shfl_sync(0xffffffffu, acc[mf][f][2], (lane + 4) & 31);
                float pc3 = __shfl_sync(0xffffffffu, acc[mf][f][3], (lane + 4) & 31);
                if ((g & 1) == 0) {
                    const int w0 = r0 >> 1;
                    const int w1 = (r0 + 8) >> 1;
                    uint32_t h0 = packbf(acc[mf][f][0], pc0);
                    Dbh[(size_t)w0 * 512 + col] = h0;
                    Dbl[(size_t)w0 * 512 + col] =
                        packbf(acc[mf][f][0] - lo_f(h0), pc0 - hi_f(h0));
                    uint32_t h1 = packbf(acc[mf][f][1], pc1);
                    Dbh[(size_t)w0 * 512 + col + 1] = h1;
                    Dbl[(size_t)w0 * 512 + col + 1] =
                        packbf(acc[mf][f][1] - lo_f(h1), pc1 - hi_f(h1));
                    uint32_t h2 = packbf(acc[mf][f][2], pc2);
                    Dbh[(size_t)w1 * 512 + col] = h2;
                    Dbl[(size_t)w1 * 512 + col] =
                        packbf(acc[mf][f][2] - lo_f(h2), pc2 - hi_f(h2));
                    uint32_t h3 = packbf(acc[mf][f][3], pc3);
                    Dbh[(size_t)w1 * 512 + col + 1] = h3;
                    Dbl[(size_t)w1 * 512 + col + 1] =
                        packbf(acc[mf][f][3] - lo_f(h3), pc3 - hi_f(h3));
                }
            }
    }
}

// ---------------------------------------------------------------------------
// Scan step: Vout[c] = Vin[c] + (c>=d ? Vin[c-d] @ S^d : 0); packed-A in/out.
// ---------------------------------------------------------------------------
__global__ __launch_bounds__(256, 2) void hmma_scan_step(
    float* __restrict__ Vout, const float* __restrict__ Vin,
    const uint32_t* __restrict__ VinAh, const uint32_t* __restrict__ VinAl,
    uint32_t* __restrict__ VoutAh, uint32_t* __restrict__ VoutAl,
    const uint32_t* __restrict__ Sbh, const uint32_t* __restrict__ Sbl, int d)
{
    const int bn = blockIdx.x * 64;
    const int bm = blockIdx.y * 128;
    const int tid = threadIdx.x;
    const int row = bm + (tid >> 1);
    const int csrc = (row >> 5) - d;
    const int asrc = (csrc >= 0) ? (csrc * 32 + (row & 31)) : row;
    const uint32_t* aph = VinAh + (size_t)asrc * 256 + (tid & 1) * 8;
    const uint32_t* apl = VinAl + (size_t)asrc * 256 + (tid & 1) * 8;
    float acc[2][4][4] = {};
    hmma_core_pp(aph, apl, Sbh + bn + (tid & 63), Sbl + bn + (tid & 63), acc);

    const int lane = tid & 31, wid = tid >> 5;
    const int g = lane >> 2, qi = lane & 3;
    const int mo = (wid >> 1) * 32, no = (wid & 1) * 32;
#pragma unroll
    for (int mf = 0; mf < 2; mf++)
#pragma unroll
        for (int f = 0; f < 4; f++) {
            const int col = bn + no + f * 8 + 2 * qi;
#pragma unroll
            for (int h = 0; h < 2; h++) {
                const int r = bm + mo + mf * 16 + g + h * 8;
                float2 e = *(const float2*)(Vin + (size_t)r * 512 + col);
                if ((r >> 5) >= d) {
                    e.x += acc[mf][f][2 * h];
                    e.y += acc[mf][f][2 * h + 1];
                }
                *(float2*)(Vout + (size_t)r * 512 + col) = e;
                write_pka(VoutAh, VoutAl, r, col, e.x, e.y);
            }
        }
}

// ---------------------------------------------------------------------------
// pass3: O[b, 16*(c+1)+t, :] += V[c] @ R^{t+1}.  grid (8, 16, 16: t)
// ---------------------------------------------------------------------------
__global__ __launch_bounds__(256, 2) void hmma_pass3(
    float* __restrict__ O,
    const uint32_t* __restrict__ VAh, const uint32_t* __restrict__ VAl,
    const uint32_t* __restrict__ Rbh, const uint32_t* __restrict__ Rbl)
{
    const int t  = blockIdx.z;
    const int bn = blockIdx.x * 64;
    const int bm = blockIdx.y * 128;
    const int tid = threadIdx.x;
    const int row = bm + (tid >> 1);
    const uint32_t* aph = VAh + (size_t)row * 256 + (tid & 1) * 8;
    const uint32_t* apl = VAl + (size_t)row * 256 + (tid & 1) * 8;
    float acc[2][4][4] = {};
    hmma_core_pp(aph, apl, Rbh + (size_t)t * SZW + bn + (tid & 63),
                 Rbl + (size_t)t * SZW + bn + (tid & 63), acc);

    const int lane = tid & 31, wid = tid >> 5;
    const int g = lane >> 2, qi = lane & 3;
    const int mo = (wid >> 1) * 32, no = (wid & 1) * 32;
#pragma unroll
    for (int mf = 0; mf < 2; mf++)
#pragma unroll
        for (int f = 0; f < 4; f++) {
            const int col = bn + no + f * 8 + 2 * qi;
#pragma unroll
            for (int h = 0; h < 2; h++) {
                const int r = bm + mo + mf * 16 + g + h * 8;
                const int cidx = r >> 5;
                if (cidx < Cc - 1) {
                    const int b = r & 31;
                    float* op = O + ((size_t)b * Tn + (size_t)(cidx + 1) * Lc + t) * 512 + col;
                    float2 e = *(float2*)op;
                    e.x += acc[mf][f][2 * h];
                    e.y += acc[mf][f][2 * h + 1];
                    *(float2*)op = e;
                }
            }
        }
}

// ---------------------------------------------------------------------------
// pack kernels
// ---------------------------------------------------------------------------
__global__ void pack_b_kernel(const float* __restrict__ src,
                              uint32_t* __restrict__ dh, uint32_t* __restrict__ dl)
{
    const int i = blockIdx.x * 256 + threadIdx.x;
    const int w = i >> 9, n = i & 511;
    const float* s = src + (size_t)(2 * w) * 512 + n;
    const float s0 = s[0], s1 = s[512];
    const uint32_t h = packbf(s0, s1);
    dh[i] = h;
    dl[i] = packbf(s0 - lo_f(h), s1 - hi_f(h));
}

__global__ void pack_a_kernel(const float* __restrict__ src,
                              uint32_t* __restrict__ dh, uint32_t* __restrict__ dl)
{
    const int i = blockIdx.x * 256 + threadIdx.x;
    const int row = i >> 8, w = i & 255;
    const float s0 = src[(size_t)row * 512 + 2 * w];
    const float s1 = src[(size_t)row * 512 + 2 * w + 1];
    const uint32_t h = packbf(s0, s1);
    dh[i] = h;
    dl[i] = packbf(s0 - lo_f(h), s1 - hi_f(h));
}

// ---------------------------------------------------------------------------
// Launch sequence
// ---------------------------------------------------------------------------
extern "C" void kernel_launch(void* const* d_in, const int* in_sizes, int n_in,
                              void* d_out, int out_size)
{
    const float* x = (const float*)d_in[0];
    const float* w = (const float*)d_in[1];
    const float* r = (const float*)d_in[2];
    float* o = (float*)d_out;
    (void)in_sizes; (void)n_in; (void)out_size;

    uint32_t *Rh, *Rl, *RAh, *RAl, *Sh, *Sl, *SAh, *SAl, *Wh, *Wl;
    uint32_t *OA0h, *OA0l, *OA1h, *OA1l;
    uint32_t *V0Ah, *V0Al, *V1Ah, *V1Al;
    float *V0, *V1;
    cudaGetSymbolAddress((void**)&Rh, g_Rh);   cudaGetSymbolAddress((void**)&Rl, g_Rl);
    cudaGetSymbolAddress((void**)&RAh, g_RAh); cudaGetSymbolAddress((void**)&RAl, g_RAl);
    cudaGetSymbolAddress((void**)&Sh, g_Sh);   cudaGetSymbolAddress((void**)&Sl, g_Sl);
    cudaGetSymbolAddress((void**)&SAh, g_SAh); cudaGetSymbolAddress((void**)&SAl, g_SAl);
    cudaGetSymbolAddress((void**)&Wh, g_Wh);   cudaGetSymbolAddress((void**)&Wl, g_Wl);
    cudaGetSymbolAddress((void**)&OA0h, g_OA0h); cudaGetSymbolAddress((void**)&OA0l, g_OA0l);
    cudaGetSymbolAddress((void**)&OA1h, g_OA1h); cudaGetSymbolAddress((void**)&OA1l, g_OA1l);
    cudaGetSymbolAddress((void**)&V0Ah, g_V0Ah); cudaGetSymbolAddress((void**)&V0Al, g_V0Al);
    cudaGetSymbolAddress((void**)&V1Ah, g_V1Ah); cudaGetSymbolAddress((void**)&V1Al, g_V1Al);
    cudaGetSymbolAddress((void**)&V0, g_V0);   cudaGetSymbolAddress((void**)&V1, g_V1);

    cudaFuncSetAttribute(hmma_gemm_xw,     cudaFuncAttributeMaxDynamicSharedMemorySize, SMEM_BYTES);
    cudaFuncSetAttribute(mega_step_kernel, cudaFuncAttributeMaxDynamicSharedMemorySize, SMEM_BYTES);
    cudaFuncSetAttribute(hmma_scan_step,   cudaFuncAttributeMaxDynamicSharedMemorySize, SMEM_BYTES);
    cudaFuncSetAttribute(hmma_pass3,       cudaFuncAttributeMaxDynamicSharedMemorySize, SMEM_BYTES);

    // Prologue packs
    pack_b_kernel<<<SZW / 256, 256>>>(w, Wh, Wl);
    pack_b_kernel<<<SZW / 256, 256>>>(r, Rh, Rl);
    pack_a_kernel<<<SZW / 256, 256>>>(r, RAh, RAl);

    // Phase A: O = X @ W (+ packed slice 0 into OA0)
    hmma_gemm_xw<<<dim3(8, M / 128), 256, SMEM_BYTES>>>(x, Wh, Wl, o, OA0h, OA0l);

    // Phase C + B: pass1 steps with ladder piggyback.
    struct Lad {
        const uint32_t *Ah, *Al, *Bh, *Bl;
        uint32_t *Cbh, *Cbl, *Cah, *Cal;
        int mt;
    };
    Lad lad[16];
    for (int t = 0; t < 16; t++)
        lad[t] = {RAh, RAl, Rh, Rl, Rh, Rl, RAh, RAl, 0};
    lad[1] = {RAh, RAl, Rh, Rl,
              Rh + 1 * SZW, Rl + 1 * SZW, RAh + 1 * SZW, RAl + 1 * SZW, 4};            // R^2
    lad[2] = {RAh, RAl, Rh + 1 * SZW, Rl + 1 * SZW,
              Rh + 2 * SZW, Rl + 2 * SZW, RAh + 2 * SZW, RAl + 2 * SZW, 8};            // R^3,R^4
    lad[3] = {RAh, RAl, Rh + 3 * SZW, Rl + 3 * SZW,
              Rh + 4 * SZW, Rl + 4 * SZW, RAh + 4 * SZW, RAl + 4 * SZW, 16};           // R^5..R^8
    lad[4] = {RAh, RAl, Rh + 7 * SZW, Rl + 7 * SZW,
              Rh + 8 * SZW, Rl + 8 * SZW, RAh + 8 * SZW, RAl + 8 * SZW, 32};           // R^9..R^16
    lad[5] = {RAh + 15 * SZW, RAl + 15 * SZW, Rh + 15 * SZW, Rl + 15 * SZW,
              Sh, Sl, SAh, SAl, 4};                                                    // S^2
    lad[6] = {SAh, SAl, Sh, Sl,
              Sh + 1 * SZW, Sl + 1 * SZW, SAh + 1 * SZW, SAl + 1 * SZW, 4};            // S^4
    lad[7] = {SAh + 1 * SZW, SAl + 1 * SZW, Sh + 1 * SZW, Sl + 1 * SZW,
              Sh + 2 * SZW, Sl + 2 * SZW, SAh + 2 * SZW, SAl + 2 * SZW, 4};            // S^8
    lad[8] = {SAh + 2 * SZW, SAl + 2 * SZW, Sh + 2 * SZW, Sl + 2 * SZW,
              Sh + 3 * SZW, Sl + 3 * SZW, SAh + 3 * SZW, SAl + 3 * SZW, 4};            // S^16
    lad[9] = {SAh + 3 * SZW, SAl + 3 * SZW, Sh + 3 * SZW, Sl + 3 * SZW,
              Sh + 4 * SZW, Sl + 4 * SZW, SAh + 4 * SZW, SAl + 4 * SZW, 4};            // S^32

    for (int t = 1; t < Lc; t++) {
        const Lad& L = lad[t];
        const uint32_t* inh = (t & 1) ? OA0h : OA1h;
        const uint32_t* inl = (t & 1) ? OA0l : OA1l;
        uint32_t* outh = (t == Lc - 1) ? V0Ah : ((t & 1) ? OA1h : OA0h);
        uint32_t* outl = (t == Lc - 1) ? V0Al : ((t & 1) ? OA1l : OA0l);
        mega_step_kernel<<<dim3(8, 16 + L.mt), 256, SMEM_BYTES>>>(
            Rh, Rl, o, t, V0, inh, inl, outh, outl,
            L.Ah, L.Al, L.Bh, L.Bl, L.Cbh, L.Cbl, L.Cah, L.Cal);
    }

    // Phase D: carry scan (Hillis-Steele over 64 chunk states)
    const float* vin = V0;           float* vout = V1;
    const uint32_t* vinAh = V0Ah;    const uint32_t* vinAl = V0Al;
    uint32_t* voutAh = V1Ah;         uint32_t* voutAl = V1Al;
    for (int i = 0; i < 6; i++) {
        const int d = 1 << i;
        const uint32_t* Sph = (i == 0) ? (Rh + (size_t)15 * SZW) : (Sh + (size_t)(i - 1) * SZW);
        const uint32_t* Spl = (i == 0) ? (Rl + (size_t)15 * SZW) : (Sl + (size_t)(i - 1) * SZW);
        hmma_scan_step<<<dim3(8, 16), 256, SMEM_BYTES>>>(
            vout, vin, vinAh, vinAl, voutAh, voutAl, Sph, Spl, d);
        { const float* tf = vin; vin = vout; vout = (float*)tf; }
        { const uint32_t* th = vinAh; vinAh = voutAh; voutAh = (uint32_t*)th; }
        { const uint32_t* tl = vinAl; vinAl = voutAl; voutAl = (uint32_t*)tl; }
    }
    // final packed V in V0A (6 swaps -> back to start)

    // Phase E: batched correction
    hmma_pass3<<<dim3(8, 16, 16), 256, SMEM_BYTES>>>(o, V0Ah, V0Al, Rh, Rl);
}

// round 13
// speedup vs baseline: 1.0837x; 1.0837x over previous
#include <cuda_runtime.h>
#include <cuda_bf16.h>
#include <cstdint>

namespace {
constexpr int Bn = 32;
constexpr int Tn = 1024;
constexpr int M  = Bn * 1024;

constexpr int Lc = 8;
constexpr int Cc = Tn / Lc;         // 128

constexpr int SZ  = 512 * 512;      // fp32 elements per matrix
constexpr int SZW = 256 * 512;      // packed bf16x2 words per matrix
constexpr int WST = 20;             // smem row stride in words
constexpr int BUFW = 7680;          // Ah 2560 | Al 2560 | Bh 1280 | Bl 1280
constexpr int SMEM_BYTES = 2 * BUFW * 4;   // 61440
}

// ---------------------------------------------------------------------------
// Static device scratch
// ---------------------------------------------------------------------------
__device__ float    g_Rf[8 * SZ];       // R^1..R^8 fp32
__device__ uint32_t g_Rh[8 * SZW];      // R^1..R^8 B-style packed hi
__device__ uint32_t g_Rl[8 * SZW];
__device__ float    g_Sf[6 * SZ];       // S^2,S^4,S^8,S^16,S^32,S^64 (S = R^8)
__device__ uint32_t g_Sh[6 * SZW];
__device__ uint32_t g_Sl[6 * SZW];
__device__ uint32_t g_Wh[SZW];
__device__ uint32_t g_Wl[SZW];
__device__ float    g_V0[Cc * Bn * 512];   // 4096 x 512
__device__ float    g_V1[Cc * Bn * 512];

// ---------------------------------------------------------------------------
// helpers
// ---------------------------------------------------------------------------
__device__ __forceinline__ uint32_t packbf(float a, float b) {
    uint32_t r;  // low half = a, high half = b
    asm("cvt.rn.bf16x2.f32 %0, %1, %2;" : "=r"(r) : "f"(b), "f"(a));
    return r;
}
__device__ __forceinline__ float lo_f(uint32_t p) { return __uint_as_float(p << 16); }
__device__ __forceinline__ float hi_f(uint32_t p) { return __uint_as_float(p & 0xFFFF0000u); }

__device__ __forceinline__ void mma16816(float* c, const uint32_t* a,
                                         uint32_t b0, uint32_t b1) {
    asm volatile(
        "mma.sync.aligned.m16n8k16.row.col.f32.bf16.bf16.f32 "
        "{%0,%1,%2,%3}, {%4,%5,%6,%7}, {%8,%9}, {%0,%1,%2,%3};"
        : "+f"(c[0]), "+f"(c[1]), "+f"(c[2]), "+f"(c[3])
        : "r"(a[0]), "r"(a[1]), "r"(a[2]), "r"(a[3]), "r"(b0), "r"(b1));
}

__device__ __forceinline__ void ldsm4(uint32_t& r0, uint32_t& r1,
                                      uint32_t& r2, uint32_t& r3, uint32_t addr) {
    asm volatile(
        "ldmatrix.sync.aligned.m8n8.x4.shared.b16 {%0,%1,%2,%3}, [%4];"
        : "=r"(r0), "=r"(r1), "=r"(r2), "=r"(r3) : "r"(addr));
}

// ---------------------------------------------------------------------------
// Double-buffered HMMA core (round-11: fp32 A converted in-kernel,
// pre-packed B, ldmatrix fragment loads).
// ---------------------------------------------------------------------------
__device__ __forceinline__ void hmma_core_bb(const float* __restrict__ arow,
                                             const uint32_t* __restrict__ bh,
                                             const uint32_t* __restrict__ bl,
                                             float acc[2][4][4])
{
    extern __shared__ uint32_t sw[];
    const uint32_t sb = (uint32_t)__cvta_generic_to_shared(sw);
    const int tid  = threadIdx.x;
    const int lane = tid & 31, wid = tid >> 5;
    const int mo = (wid >> 1) * 32, no = (wid & 1) * 32;

    const int sar = tid >> 1;
    const int saw = (tid & 1) * 8;
    const int sbw = (tid >> 6) * 4;

    const int aoffw = (lane & 15) * WST + (lane >> 4) * 4;
    const int jj = lane >> 3, iL = lane & 7;
    const int boffw = ((jj >> 1) * 8 + iL) * WST + (jj & 1) * 4;

    float af[16];
    uint32_t bhw[4], blw[4];

    auto LOAD = [&](int kc) {
        const float* ap = arow + kc * 32;
        float4 v;
        v = *(const float4*)(ap + 0);  af[0] = v.x;  af[1] = v.y;  af[2] = v.z;  af[3] = v.w;
        v = *(const float4*)(ap + 4);  af[4] = v.x;  af[5] = v.y;  af[6] = v.z;  af[7] = v.w;
        v = *(const float4*)(ap + 8);  af[8] = v.x;  af[9] = v.y;  af[10] = v.z; af[11] = v.w;
        v = *(const float4*)(ap + 12); af[12] = v.x; af[13] = v.y; af[14] = v.z; af[15] = v.w;
        const int off = (kc * 16 + sbw) * 512;
        bhw[0] = bh[off];        bhw[1] = bh[off + 512];
        bhw[2] = bh[off + 1024]; bhw[3] = bh[off + 1536];
        blw[0] = bl[off];        blw[1] = bl[off + 512];
        blw[2] = bl[off + 1024]; blw[3] = bl[off + 1536];
    };

    auto STORE = [&](int bi) {
        uint32_t h[8], l[8];
#pragma unroll
        for (int j = 0; j < 8; j++) {
            h[j] = packbf(af[2 * j], af[2 * j + 1]);
            l[j] = packbf(af[2 * j] - lo_f(h[j]), af[2 * j + 1] - hi_f(h[j]));
        }
        uint32_t* pA = sw + bi * BUFW + sar * WST + saw;
        *(uint4*)pA        = make_uint4(h[0], h[1], h[2], h[3]);
        *(uint4*)(pA + 4)  = make_uint4(h[4], h[5], h[6], h[7]);
        uint32_t* pAl = pA + 2560;
        *(uint4*)pAl       = make_uint4(l[0], l[1], l[2], l[3]);
        *(uint4*)(pAl + 4) = make_uint4(l[4], l[5], l[6], l[7]);
        uint32_t* pB = sw + bi * BUFW + 5120 + (tid & 63) * WST + sbw;
        *(uint4*)pB          = make_uint4(bhw[0], bhw[1], bhw[2], bhw[3]);
        *(uint4*)(pB + 1280) = make_uint4(blw[0], blw[1], blw[2], blw[3]);
    };

    auto COMPUTE = [&](int bi) {
        const uint32_t base = sb + (uint32_t)(bi * BUFW) * 4u;
#pragma unroll
        for (int s = 0; s < 2; s++) {
            const int ws = s * 8;
            uint32_t aH[2][4], aL[2][4];
#pragma unroll
            for (int mf = 0; mf < 2; mf++) {
                const uint32_t wa = base + (uint32_t)(((mo + mf * 16) * WST + ws + aoffw) * 4);
                ldsm4(aH[mf][0], aH[mf][1], aH[mf][2], aH[mf][3], wa);
                ldsm4(aL[mf][0], aL[mf][1], aL[mf][2], aL[mf][3], wa + 2560u * 4u);
            }
#pragma unroll
            for (int p = 0; p < 2; p++) {
                const uint32_t wb = base +
                    (uint32_t)((5120 + (no + p * 16) * WST + ws + boffw) * 4);
                uint32_t h0, h1, h2, h3, l0, l1, l2, l3;
                ldsm4(h0, h1, h2, h3, wb);
                ldsm4(l0, l1, l2, l3, wb + 1280u * 4u);
#pragma unroll
                for (int mf = 0; mf < 2; mf++) {
                    mma16816(acc[mf][2 * p],     aH[mf], h0, h1);
                    mma16816(acc[mf][2 * p],     aH[mf], l0, l1);
                    mma16816(acc[mf][2 * p],     aL[mf], h0, h1);
                    mma16816(acc[mf][2 * p + 1], aH[mf], h2, h3);
                    mma16816(acc[mf][2 * p + 1], aH[mf], l2, l3);
                    mma16816(acc[mf][2 * p + 1], aL[mf], h2, h3);
                }
            }
        }
    };

    LOAD(0); STORE(0); __syncthreads();
    int cur = 0;
    for (int kc = 0; kc < 16; kc++) {
        if (kc < 15) LOAD(kc + 1);
        COMPUTE(cur);
        if (kc < 15) { STORE(cur ^ 1); __syncthreads(); cur ^= 1; }
    }
}

// ladder epilogue: fp32 C + B-style packed (row-pair shuffle)
__device__ __forceinline__ void ladder_epilogue(
    const float acc[2][4][4], int mrow, int bn,
    float* __restrict__ Cz, uint32_t* __restrict__ Dh, uint32_t* __restrict__ Dl)
{
    const int tid = threadIdx.x;
    const int lane = tid & 31, wid = tid >> 5;
    const int g = lane >> 2, qi = lane & 3;
    const int mo = (wid >> 1) * 32, no = (wid & 1) * 32;
#pragma unroll
    for (int mf = 0; mf < 2; mf++)
#pragma unroll
        for (int f = 0; f < 4; f++) {
            const int r0  = mrow + mo + mf * 16 + g;
            const int col = bn + no + f * 8 + 2 * qi;
            *(float2*)(Cz + (size_t)r0 * 512 + col) =
                make_float2(acc[mf][f][0], acc[mf][f][1]);
            *(float2*)(Cz + (size_t)(r0 + 8) * 512 + col) =
                make_float2(acc[mf][f][2], acc[mf][f][3]);

            float pc0 = __shfl_sync(0xffffffffu, acc[mf][f][0], (lane + 4) & 31);
            float pc1 = __shfl_sync(0xffffffffu, acc[mf][f][1], (lane + 4) & 31);
            float pc2 = __shfl_sync(0xffffffffu, acc[mf][f][2], (lane + 4) & 31);
            float pc3 = __shfl_sync(0xffffffffu, acc[mf][f][3], (lane + 4) & 31);
            if ((g & 1) == 0) {
                const int w0 = r0 >> 1;
                const int w1 = (r0 + 8) >> 1;
                uint32_t h0 = packbf(acc[mf][f][0], pc0);
                Dh[(size_t)w0 * 512 + col] = h0;
                Dl[(size_t)w0 * 512 + col] =
                    packbf(acc[mf][f][0] - lo_f(h0), pc0 - hi_f(h0));
                uint32_t h1 = packbf(acc[mf][f][1], pc1);
                Dh[(size_t)w0 * 512 + col + 1] = h1;
                Dl[(size_t)w0 * 512 + col + 1] =
                    packbf(acc[mf][f][1] - lo_f(h1), pc1 - hi_f(h1));
                uint32_t h2 = packbf(acc[mf][f][2], pc2);
                Dh[(size_t)w1 * 512 + col] = h2;
                Dl[(size_t)w1 * 512 + col] =
                    packbf(acc[mf][f][2] - lo_f(h2), pc2 - hi_f(h2));
                uint32_t h3 = packbf(acc[mf][f][3], pc3);
                Dh[(size_t)w1 * 512 + col + 1] = h3;
                Dl[(size_t)w1 * 512 + col + 1] =
                    packbf(acc[mf][f][3] - lo_f(h3), pc3 - hi_f(h3));
            }
        }
}

// ---------------------------------------------------------------------------
// generic C = A @ B (fp32 out).  grid (n/64, m/128).  Used for XW.
// ---------------------------------------------------------------------------
__global__ __launch_bounds__(256, 2) void hmma_gemm_bb(
    const float* __restrict__ A, const uint32_t* __restrict__ Bh,
    const uint32_t* __restrict__ Bl, float* __restrict__ C)
{
    const int bn = blockIdx.x * 64;
    const int bm = blockIdx.y * 128;
    const int tid = threadIdx.x;
    const float* arow = A + (size_t)(bm + (tid >> 1)) * 512 + (tid & 1) * 16;
    float acc[2][4][4] = {};
    hmma_core_bb(arow, Bh + bn + (tid & 63), Bl + bn + (tid & 63), acc);

    const int lane = tid & 31, wid = tid >> 5;
    const int g = lane >> 2, qi = lane & 3;
    const int mo = (wid >> 1) * 32, no = (wid & 1) * 32;
#pragma unroll
    for (int mf = 0; mf < 2; mf++)
#pragma unroll
        for (int f = 0; f < 4; f++) {
            const int r0  = bm + mo + mf * 16 + g;
            const int col = bn + no + f * 8 + 2 * qi;
            *(float2*)(C + (size_t)r0 * 512 + col) =
                make_float2(acc[mf][f][0], acc[mf][f][1]);
            *(float2*)(C + (size_t)(r0 + 8) * 512 + col) =
                make_float2(acc[mf][f][2], acc[mf][f][3]);
        }
}

// ---------------------------------------------------------------------------
// Mega pass1 step: y < 32 -> pass1 tile; y >= 32 -> ladder tile.
// pass1: O[b, c*8+t, :] += O[b, c*8+t-1, :] @ R   (4096 rows; c=0..127)
// t == Lc-1 also seeds V0.
// ---------------------------------------------------------------------------
__global__ __launch_bounds__(256, 2) void mega_step_kernel(
    const uint32_t* __restrict__ Rh, const uint32_t* __restrict__ Rl,
    float* __restrict__ O, int t, float* __restrict__ V0,
    const float* __restrict__ LA,
    const uint32_t* __restrict__ LBh, const uint32_t* __restrict__ LBl,
    float* __restrict__ LCf, uint32_t* __restrict__ LCh, uint32_t* __restrict__ LCl)
{
    const int bn  = blockIdx.x * 64;
    const int tid = threadIdx.x;

    if (blockIdx.y < 32) {
        const int bm = blockIdx.y * 128;
        const int srow = bm + (tid >> 1);
        const float* arow = O + ((size_t)(srow & 31) * Tn + (size_t)(srow >> 5) * Lc + (t - 1)) * 512
                            + (tid & 1) * 16;
        float acc[2][4][4] = {};
        hmma_core_bb(arow, Rh + bn + (tid & 63), Rl + bn + (tid & 63), acc);

        const int lane = tid & 31, wid = tid >> 5;
        const int g = lane >> 2, qi = lane & 3;
        const int mo = (wid >> 1) * 32, no = (wid & 1) * 32;
#pragma unroll
        for (int mf = 0; mf < 2; mf++)
#pragma unroll
            for (int f = 0; f < 4; f++) {
                const int col = bn + no + f * 8 + 2 * qi;
#pragma unroll
                for (int h = 0; h < 2; h++) {
                    const int r = bm + mo + mf * 16 + g + h * 8;
                    float* op = O + ((size_t)(r & 31) * Tn + (size_t)(r >> 5) * Lc + t) * 512 + col;
                    float2 e = *(float2*)op;
                    e.x += acc[mf][f][2 * h];
                    e.y += acc[mf][f][2 * h + 1];
                    *(float2*)op = e;
                    if (t == Lc - 1)
                        *(float2*)(V0 + (size_t)r * 512 + col) = e;
                }
            }
    } else {
        const int y2 = blockIdx.y - 32;
        const int z  = y2 >> 2;
        const int mrow = (y2 & 3) * 128;
        const float* arow = LA + (size_t)z * SZ + (size_t)(mrow + (tid >> 1)) * 512 + (tid & 1) * 16;
        float acc[2][4][4] = {};
        hmma_core_bb(arow, LBh + bn + (tid & 63), LBl + bn + (tid & 63), acc);
        ladder_epilogue(acc, mrow, bn, LCf + (size_t)z * SZ,
                        LCh + (size_t)z * SZW, LCl + (size_t)z * SZW);
    }
}

// ---------------------------------------------------------------------------
// Scan step (+ ladder piggyback): y < 32 -> scan; y >= 32 -> ladder.
// scan: Vout[c] = Vin[c] + (c>=d ? Vin[c-d] @ S^d : 0)   (4096 rows)
// ---------------------------------------------------------------------------
__global__ __launch_bounds__(256, 2) void hmma_scan_step(
    float* __restrict__ Vout, const float* __restrict__ Vin,
    const uint32_t* __restrict__ Sh, const uint32_t* __restrict__ Sl, int d,
    const float* __restrict__ LA,
    const uint32_t* __restrict__ LBh, const uint32_t* __restrict__ LBl,
    float* __restrict__ LCf, uint32_t* __restrict__ LCh, uint32_t* __restrict__ LCl)
{
    const int bn  = blockIdx.x * 64;
    const int tid = threadIdx.x;

    if (blockIdx.y < 32) {
        const int bm = blockIdx.y * 128;
        const int srow = bm + (tid >> 1);
        const int csrc = (srow >> 5) - d;
        const int asrc = (csrc >= 0) ? (csrc * 32 + (srow & 31)) : srow;
        const float* arow = Vin + (size_t)asrc * 512 + (tid & 1) * 16;
        float acc[2][4][4] = {};
        hmma_core_bb(arow, Sh + bn + (tid & 63), Sl + bn + (tid & 63), acc);

        const int lane = tid & 31, wid = tid >> 5;
        const int g = lane >> 2, qi = lane & 3;
        const int mo = (wid >> 1) * 32, no = (wid & 1) * 32;
#pragma unroll
        for (int mf = 0; mf < 2; mf++)
#pragma unroll
            for (int f = 0; f < 4; f++) {
                const int col = bn + no + f * 8 + 2 * qi;
#pragma unroll
                for (int h = 0; h < 2; h++) {
                    const int r = bm + mo + mf * 16 + g + h * 8;
                    float2 e = *(const float2*)(Vin + (size_t)r * 512 + col);
                    if ((r >> 5) >= d) {
                        e.x += acc[mf][f][2 * h];
                        e.y += acc[mf][f][2 * h + 1];
                    }
                    *(float2*)(Vout + (size_t)r * 512 + col) = e;
                }
            }
    } else {
        const int y2 = blockIdx.y - 32;
        const int z  = y2 >> 2;
        const int mrow = (y2 & 3) * 128;
        const float* arow = LA + (size_t)z * SZ + (size_t)(mrow + (tid >> 1)) * 512 + (tid & 1) * 16;
        float acc[2][4][4] = {};
        hmma_core_bb(arow, LBh + bn + (tid & 63), LBl + bn + (tid & 63), acc);
        ladder_epilogue(acc, mrow, bn, LCf + (size_t)z * SZ,
                        LCh + (size_t)z * SZW, LCl + (size_t)z * SZW);
    }
}

// ---------------------------------------------------------------------------
// pass3: O[b, 8*(c+1)+t, :] += V[c] @ R^{t+1}.  grid (8, 32, 8: t)
// ---------------------------------------------------------------------------
__global__ __launch_bounds__(256, 2) void hmma_pass3_bb(
    float* __restrict__ O, const float* __restrict__ V,
    const uint32_t* __restrict__ Rh, const uint32_t* __restrict__ Rl)
{
    const int t  = blockIdx.z;
    const int bn = blockIdx.x * 64;
    const int bm = blockIdx.y * 128;
    const int tid = threadIdx.x;
    const float* arow = V + (size_t)(bm + (tid >> 1)) * 512 + (tid & 1) * 16;
    float acc[2][4][4] = {};
    hmma_core_bb(arow, Rh + (size_t)t * SZW + bn + (tid & 63),
                 Rl + (size_t)t * SZW + bn + (tid & 63), acc);

    const int lane = tid & 31, wid = tid >> 5;
    const int g = lane >> 2, qi = lane & 3;
    const int mo = (wid >> 1) * 32, no = (wid & 1) * 32;
#pragma unroll
    for (int mf = 0; mf < 2; mf++)
#pragma unroll
        for (int f = 0; f < 4; f++) {
            const int col = bn + no + f * 8 + 2 * qi;
#pragma unroll
            for (int h = 0; h < 2; h++) {
                const int r = bm + mo + mf * 16 + g + h * 8;
                const int cidx = r >> 5;       // = c-1
                if (cidx < Cc - 1) {
                    const int b = r & 31;
                    float* op = O + ((size_t)b * Tn + (size_t)(cidx + 1) * Lc + t) * 512 + col;
                    float2 e = *(float2*)op;
                    e.x += acc[mf][f][2 * h];
                    e.y += acc[mf][f][2 * h + 1];
                    *(float2*)op = e;
                }
            }
        }
}

// ---------------------------------------------------------------------------
// utilities
// ---------------------------------------------------------------------------
__global__ void pack_b_kernel(const float* __restrict__ src,
                              uint32_t* __restrict__ dh, uint32_t* __restrict__ dl)
{
    const int i = blockIdx.x * 256 + threadIdx.x;
    const int w = i >> 9, n = i & 511;
    const float* s = src + (size_t)(2 * w) * 512 + n;
    const float s0 = s[0], s1 = s[512];
    const uint32_t h = packbf(s0, s1);
    dh[i] = h;
    dl[i] = packbf(s0 - lo_f(h), s1 - hi_f(h));
}

__global__ void copy_floats_kernel(float* __restrict__ dst,
                                   const float* __restrict__ src, int n4)
{
    int i = blockIdx.x * blockDim.x + threadIdx.x;
    if (i < n4) ((float4*)dst)[i] = ((const float4*)src)[i];
}

// ---------------------------------------------------------------------------
// Launch sequence
// ---------------------------------------------------------------------------
extern "C" void kernel_launch(void* const* d_in, const int* in_sizes, int n_in,
                              void* d_out, int out_size)
{
    const float* x = (const float*)d_in[0];
    const float* w = (const float*)d_in[1];
    const float* r = (const float*)d_in[2];
    float* o = (float*)d_out;
    (void)in_sizes; (void)n_in; (void)out_size;

    float *Rf, *Sf, *V0, *V1;
    uint32_t *Rh, *Rl, *Sh, *Sl, *Wh, *Wl;
    cudaGetSymbolAddress((void**)&Rf, g_Rf);
    cudaGetSymbolAddress((void**)&Rh, g_Rh);
    cudaGetSymbolAddress((void**)&Rl, g_Rl);
    cudaGetSymbolAddress((void**)&Sf, g_Sf);
    cudaGetSymbolAddress((void**)&Sh, g_Sh);
    cudaGetSymbolAddress((void**)&Sl, g_Sl);
    cudaGetSymbolAddress((void**)&Wh, g_Wh);
    cudaGetSymbolAddress((void**)&Wl, g_Wl);
    cudaGetSymbolAddress((void**)&V0, g_V0);
    cudaGetSymbolAddress((void**)&V1, g_V1);

    cudaFuncSetAttribute(hmma_gemm_bb,     cudaFuncAttributeMaxDynamicSharedMemorySize, SMEM_BYTES);
    cudaFuncSetAttribute(mega_step_kernel, cudaFuncAttributeMaxDynamicSharedMemorySize, SMEM_BYTES);
    cudaFuncSetAttribute(hmma_scan_step,   cudaFuncAttributeMaxDynamicSharedMemorySize, SMEM_BYTES);
    cudaFuncSetAttribute(hmma_pass3_bb,    cudaFuncAttributeMaxDynamicSharedMemorySize, SMEM_BYTES);

    // Prologue: pack W and R (B-style), seed Rf slot 0 with R^1.
    pack_b_kernel<<<SZW / 256, 256>>>(w, Wh, Wl);
    pack_b_kernel<<<SZW / 256, 256>>>(r, Rh, Rl);
    copy_floats_kernel<<<SZ / 4 / 256, 256>>>(Rf, r, SZ / 4);

    // Phase A: O = X @ W
    hmma_gemm_bb<<<dim3(8, M / 128), 256, SMEM_BYTES>>>(x, Wh, Wl, o);

    // Ladder schedule.  S = R^8.  Sf slots: 0:S^2 1:S^4 2:S^8 3:S^16 4:S^32 5:S^64
    struct Lad { const float* A; const uint32_t *Bh, *Bl; float* Cf; uint32_t *Ch, *Cl; int mt; };
    Lad dummy = {r, Rh, Rl, Rf, Rh, Rl, 0};

    Lad lad1[8];
    for (int t = 0; t < 8; t++) lad1[t] = dummy;
    lad1[1] = {r,            Rh,            Rl,            Rf + (size_t)1 * SZ, Rh + 1 * SZW, Rl + 1 * SZW, 4};   // R^2
    lad1[2] = {Rf,           Rh + 1 * SZW,  Rl + 1 * SZW,  Rf + (size_t)2 * SZ, Rh + 2 * SZW, Rl + 2 * SZW, 8};   // R^3,R^4
    lad1[3] = {Rf,           Rh + 3 * SZW,  Rl + 3 * SZW,  Rf + (size_t)4 * SZ, Rh + 4 * SZW, Rl + 4 * SZW, 16};  // R^5..R^8
    lad1[4] = {Rf + 7 * SZ,  Rh + 7 * SZW,  Rl + 7 * SZW,  Sf,                  Sh,           Sl,           4};   // S^2
    lad1[5] = {Sf,           Sh,            Sl,            Sf + (size_t)1 * SZ, Sh + 1 * SZW, Sl + 1 * SZW, 4};   // S^4
    lad1[6] = {Sf + 1 * SZ,  Sh + 1 * SZW,  Sl + 1 * SZW,  Sf + (size_t)2 * SZ, Sh + 2 * SZW, Sl + 2 * SZW, 4};   // S^8
    lad1[7] = {Sf + 2 * SZ,  Sh + 2 * SZW,  Sl + 2 * SZW,  Sf + (size_t)3 * SZ, Sh + 3 * SZW, Sl + 3 * SZW, 4};   // S^16

    // Phase C + B: 7 pass1 steps with ladder piggyback
    for (int t = 1; t < Lc; t++) {
        const Lad& L = lad1[t];
        mega_step_kernel<<<dim3(8, 32 + L.mt), 256, SMEM_BYTES>>>(
            Rh, Rl, o, t, V0, L.A, L.Bh, L.Bl, L.Cf, L.Ch, L.Cl);
    }

    // Phase D: carry scan (Hillis-Steele over 128 chunk states, 7 steps),
    // with S^32 / S^64 squarings piggybacked on steps 0 / 1.
    Lad lads[7];
    for (int i = 0; i < 7; i++) lads[i] = dummy;
    lads[0] = {Sf + 3 * SZ, Sh + 3 * SZW, Sl + 3 * SZW, Sf + (size_t)4 * SZ, Sh + 4 * SZW, Sl + 4 * SZW, 4};  // S^32
    lads[1] = {Sf + 4 * SZ, Sh + 4 * SZW, Sl + 4 * SZW, Sf + (size_t)5 * SZ, Sh + 5 * SZW, Sl + 5 * SZW, 4};  // S^64

    const float* vin = V0;
    float* vout = V1;
    for (int i = 0; i < 7; i++) {
        const int d = 1 << i;
        const uint32_t* Sph = (i == 0) ? (Rh + (size_t)7 * SZW) : (Sh + (size_t)(i - 1) * SZW);
        const uint32_t* Spl = (i == 0) ? (Rl + (size_t)7 * SZW) : (Sl + (size_t)(i - 1) * SZW);
        const Lad& L = lads[i];
        hmma_scan_step<<<dim3(8, 32 + L.mt), 256, SMEM_BYTES>>>(
            vout, vin, Sph, Spl, d, L.A, L.Bh, L.Bl, L.Cf, L.Ch, L.Cl);
        const float* tmp = vin; vin = vout; vout = (float*)tmp;
    }

    // Phase E: batched correction (t = 0..7)
    hmma_pass3_bb<<<dim3(8, 32, Lc), 256, SMEM_BYTES>>>(o, vin, Rh, Rl);
}